// round 11
// baseline (speedup 1.0000x reference)
#include <cuda_runtime.h>

#define B_TOT 8192
#define T_STEPS 256
#define SD 12          // state dim
#define AD 4           // action dim
#define DD 16          // D = SD + AD
#define HH 16          // hidden
#define GG 64          // 4*H

#define WPB 2                      // warps (= batches) per block
#define THREADS (WPB * 32)
#define NBLOCKS (B_TOT / WPB)

typedef unsigned long long ull;

// Per-lane packed weights. lane = hi*16 + j owns gate rows r0 (hi=0: i_j, hi=1: f_j)
// and r1 (hi=0: g_j, hi=1: o_j).
__device__ float2 g_WxL[32 * 16];
__device__ float2 g_WhL[32 * 16];
__device__ float4 g_SBL[32];                    // (S_r0, S_r1, B_r0, B_r1)
__device__ __align__(16) float2 g_WoL[SD * 8];  // W_out packed pairs, row-major
__device__ float  g_boL[SD];

__global__ void vm_prep(const float* __restrict__ ln_gamma,
                        const float* __restrict__ ln_beta,
                        const float* __restrict__ W_in,   // [H][D]
                        const float* __restrict__ b_in,   // [H]
                        const float* __restrict__ W_ih,   // [G][H]
                        const float* __restrict__ W_hh,   // [G][H]
                        const float* __restrict__ b_ih,
                        const float* __restrict__ b_hh,
                        const float* __restrict__ W_out,  // [SD][H]
                        const float* __restrict__ b_out)
{
    int r = threadIdx.x;   // gate row 0..63
    if (r < GG) {
        int j    = r & 15;
        int hi   = (r >> 4) & 1;
        int s    = r >> 5;
        int lane = hi * 16 + j;
        float wp[DD];
        float S = 0.f, bB = 0.f;
        for (int d = 0; d < DD; d++) {
            float acc = 0.f;
            for (int k = 0; k < HH; k++) acc += W_ih[r * HH + k] * W_in[k * DD + d];
            wp[d] = acc * ln_gamma[d];             // fold gamma
            bB += acc * ln_beta[d];                // fold beta
            S += wp[d];
        }
        float bi = 0.f;
        for (int k = 0; k < HH; k++) bi += W_ih[r * HH + k] * b_in[k];
        ((float*)&g_SBL[lane])[s]     = S;
        ((float*)&g_SBL[lane])[2 + s] = bB + bi + b_ih[r] + b_hh[r];
        for (int p = 0; p < 8; p++) {
            g_WxL[lane * 16 + s * 8 + p] = make_float2(wp[2 * p], wp[2 * p + 1]);
            g_WhL[lane * 16 + s * 8 + p] = make_float2(W_hh[r * HH + 2 * p],
                                                       W_hh[r * HH + 2 * p + 1]);
        }
    }
    if (r < SD) {
        for (int p = 0; p < 8; p++)
            g_WoL[r * 8 + p] = make_float2(W_out[r * HH + 2 * p], W_out[r * HH + 2 * p + 1]);
        g_boL[r] = b_out[r];
    }
}

__device__ __forceinline__ void fma2(ull& acc, ull w, ull x) {
    asm("fma.rn.f32x2 %0, %1, %2, %0;" : "+l"(acc) : "l"(w), "l"(x));
}
__device__ __forceinline__ void add2(ull& acc, ull x) {
    asm("add.rn.f32x2 %0, %0, %1;" : "+l"(acc) : "l"(x));
}
__device__ __forceinline__ ull mul2(ull a, ull b) {
    ull r; asm("mul.rn.f32x2 %0, %1, %2;" : "=l"(r) : "l"(a), "l"(b)); return r;
}
__device__ __forceinline__ float2 up(ull v) {
    float2 r; asm("mov.b64 {%0, %1}, %2;" : "=f"(r.x), "=f"(r.y) : "l"(v)); return r;
}
__device__ __forceinline__ float ex2_(float x) {
    float r; asm("ex2.approx.f32 %0, %1;" : "=f"(r) : "f"(x)); return r;
}
__device__ __forceinline__ float rcp_(float x) {
    float r; asm("rcp.approx.f32 %0, %1;" : "=f"(r) : "f"(x)); return r;
}
__device__ __forceinline__ float sigm(float x) {
    return rcp_(1.f + ex2_(x * -1.44269504f));
}
__device__ __forceinline__ float tanh5(float x) {
    return fmaf(-2.f, rcp_(1.f + ex2_(x * 2.88539008f)), 1.f);
}

__global__ __launch_bounds__(THREADS, 10) void vm_main(
    const float* __restrict__ init_state,   // [B][1][SD]
    const float* __restrict__ commands,     // [B][T][AD]
    float* __restrict__ out)                // [B][T][SD]
{
    __shared__ __align__(16) float xbuf[WPB][16];
    __shared__ __align__(16) float hbuf[WPB][16];
    __shared__ ulonglong2 sWo[SD * 5];   // stride-5 quads: <=2-way bank conflict
    __shared__ float sbo[SD];

    int tid  = threadIdx.x;
    int w    = tid >> 5;     // warp in block = local batch
    int lane = tid & 31;
    int j    = lane & 15;
    int hi   = lane >> 4;
    int b    = blockIdx.x * WPB + w;

    // stage W_out into padded smem
    {
        const ulonglong2* gq = (const ulonglong2*)g_WoL;
        for (int i = tid; i < SD * 4; i += THREADS)
            sWo[(i >> 2) * 5 + (i & 3)] = gq[i];
        for (int i = tid; i < SD; i += THREADS) sbo[i] = g_boL[i];
    }

    // loop-invariant gate weights in registers
    ull Wx[16], Wh[16];
    const ull* wx = (const ull*)g_WxL + lane * 16;
    const ull* wh = (const ull*)g_WhL + lane * 16;
    #pragma unroll
    for (int i = 0; i < 16; i++) { Wx[i] = wx[i]; Wh[i] = wh[i]; }
    float4 SB = g_SBL[lane];

    int  jw      = (j < SD) ? j : 0;
    bool stlane  = (hi == 0) && (j < SD);
    bool cmdlane = (hi == 1) && (j >= SD);
    float kk     = hi ? -1.44269504f : 2.88539008f;   // sigm vs tanh exponent scale

    float st = 0.f;
    if (stlane) st = init_state[b * SD + j];
    float c = 0.f;
    ull a0h = 0ULL, a1h = 0ULL;     // Wh·h carried from previous step (h(-1)=0)

    const float* cmdp = commands + (size_t)b * (T_STEPS * AD);
    float*       outp = out      + (size_t)b * (T_STEPS * SD);
    int ci = j - SD;   // command component for cmdlane

    // x for t=0 ; prefetch cmds for t=1,2
    if (stlane)  xbuf[w][j] = st;
    if (cmdlane) xbuf[w][j] = cmdp[ci];
    float cb0 = 0.f, cb1 = 0.f;
    if (cmdlane) {
        cb0 = cmdp[1 * AD + ci];
        cb1 = cmdp[2 * AD + ci];
    }
    __syncthreads();   // sWo + xbuf visible

    const ulonglong2* xq4 = (const ulonglong2*)xbuf[w];
    const ulonglong2* hq4 = (const ulonglong2*)hbuf[w];
    const ulonglong2* wop = sWo + jw * 5 + hi * 2;   // this lane's 2 Wout quads (split-K)
    float bo = sbo[jw];

    int  p16 = (j >= 1 && j <= 6) ? (j + ((j & 1) ? 1 : -1)) : j;
    bool isc = (j >= 1 && j <= 6);

    auto step = [&](int t, float cnext) {
        // ---- x-pass: stream x quads, fuse LN stats + x gate dots ----
        ulonglong2 v = xq4[0];
        ull sa  = v.x;
        ull qa  = mul2(v.x, v.x);
        add2(sa, v.y); fma2(qa, v.y, v.y);
        ull a0x = mul2(Wx[0], v.x); fma2(a0x, Wx[1], v.y);
        ull a1x = mul2(Wx[8], v.x); fma2(a1x, Wx[9], v.y);
        #pragma unroll
        for (int q = 1; q < 4; q++) {
            v = xq4[q];
            add2(sa, v.x); fma2(qa, v.x, v.x);
            add2(sa, v.y); fma2(qa, v.y, v.y);
            fma2(a0x, Wx[2 * q],     v.x); fma2(a0x, Wx[2 * q + 1],     v.y);
            fma2(a1x, Wx[8 + 2 * q], v.x); fma2(a1x, Wx[8 + 2 * q + 1], v.y);
        }
        float2 su = up(sa), qu = up(qa);
        float mu   = (su.x + su.y) * 0.0625f;
        float var  = fmaf(-mu, mu, (qu.x + qu.y) * 0.0625f);
        float rstd = rsqrtf(var + 1e-5f);

        float2 u0 = up(a0x), u1 = up(a1x);
        float2 v0 = up(a0h), v1p = up(a1h);   // h-dot carried from previous step
        float g0 = fmaf(rstd, fmaf(-mu, SB.x, u0.x + u0.y), SB.z) + (v0.x + v0.y);
        float g1 = fmaf(rstd, fmaf(-mu, SB.y, u1.x + u1.y), SB.w) + (v1p.x + v1p.y);

        // ---- activations: hi=0 -> (sig i, tanh g) ; hi=1 -> (sig f, sig o) ----
        float sA = sigm(g0);
        float r1 = rcp_(1.f + ex2_(g1 * kk));
        float v1 = hi ? r1 : fmaf(-2.f, r1, 1.f);
        float a  = sA * v1;                               // sig(i)*tanh(g) on hi=0
        float send1 = hi ? sA : a;
        float fs = __shfl_xor_sync(0xffffffffu, send1, 16);  // hi=0 gets sig(f)
        float os = __shfl_xor_sync(0xffffffffu, v1, 16);     // hi=0 gets sig(o)
        c = fmaf(fs, c, a);
        float h = os * tanh5(c);

        if (hi == 0) hbuf[w][j] = h;
        __syncwarp();

        // ---- h-pass: next step's Wh·h dots + split-K Wout (this lane: k-quads 2hi,2hi+1) ----
        // lane-rotated quad order: first two iterations read this lane's Wout k-range.
        ulonglong2 hv, wv;
        int q0 = 2 * hi;
        hv = hq4[q0];
        a0h = mul2(Wh[2 * q0], hv.x); fma2(a0h, Wh[2 * q0 + 1], hv.y);
        a1h = mul2(Wh[8 + 2 * q0], hv.x); fma2(a1h, Wh[8 + 2 * q0 + 1], hv.y);
        wv = wop[0];
        ull ao = mul2(wv.x, hv.x); fma2(ao, wv.y, hv.y);

        int q1 = q0 + 1;
        hv = hq4[q1];
        fma2(a0h, Wh[2 * q1], hv.x); fma2(a0h, Wh[2 * q1 + 1], hv.y);
        fma2(a1h, Wh[8 + 2 * q1], hv.x); fma2(a1h, Wh[8 + 2 * q1 + 1], hv.y);
        wv = wop[1];
        fma2(ao, wv.x, hv.x); fma2(ao, wv.y, hv.y);

        int q2 = (q0 + 2) & 3;
        hv = hq4[q2];
        fma2(a0h, Wh[2 * q2], hv.x); fma2(a0h, Wh[2 * q2 + 1], hv.y);
        fma2(a1h, Wh[8 + 2 * q2], hv.x); fma2(a1h, Wh[8 + 2 * q2 + 1], hv.y);

        int q3 = (q0 + 3) & 3;
        hv = hq4[q3];
        fma2(a0h, Wh[2 * q3], hv.x); fma2(a0h, Wh[2 * q3 + 1], hv.y);
        fma2(a1h, Wh[8 + 2 * q3], hv.x); fma2(a1h, Wh[8 + 2 * q3 + 1], hv.y);

        // combine Wout split-K across half-warps
        float2 aof = up(ao);
        float aos = aof.x + aof.y;
        float aoo = __shfl_xor_sync(0xffffffffu, aos, 16);
        st = st + (aos + aoo) + bo;

        // sincos renorm, branch-free
        float other = __shfl_sync(0xffffffffu, st, p16, 16);
        float rn = rsqrtf(fmaf(st, st, other * other));
        st = isc ? st * rn : st;

        if (stlane) { outp[t * SD + j] = st; xbuf[w][j] = st; }
        if (cmdlane) xbuf[w][j] = cnext;
        __syncwarp();
    };

    for (int tb = 0; tb < T_STEPS; tb += 2) {
        float n0 = 0.f, n1 = 0.f;
        if (cmdlane) {
            int i0 = tb + 3; if (i0 > T_STEPS - 1) i0 = T_STEPS - 1;
            int i1 = tb + 4; if (i1 > T_STEPS - 1) i1 = T_STEPS - 1;
            n0 = cmdp[i0 * AD + ci];
            n1 = cmdp[i1 * AD + ci];
        }
        step(tb + 0, cb0);
        step(tb + 1, cb1);
        cb0 = n0; cb1 = n1;
    }
}

extern "C" void kernel_launch(void* const* d_in, const int* in_sizes, int n_in,
                              void* d_out, int out_size) {
    const float* init_state = (const float*)d_in[0];
    const float* commands   = (const float*)d_in[1];
    const float* ln_gamma   = (const float*)d_in[2];
    const float* ln_beta    = (const float*)d_in[3];
    const float* W_in       = (const float*)d_in[4];
    const float* b_in       = (const float*)d_in[5];
    const float* W_ih       = (const float*)d_in[6];
    const float* W_hh       = (const float*)d_in[7];
    const float* b_ih       = (const float*)d_in[8];
    const float* b_hh       = (const float*)d_in[9];
    const float* W_out      = (const float*)d_in[10];
    const float* b_out      = (const float*)d_in[11];
    float* out = (float*)d_out;

    vm_prep<<<1, 64>>>(ln_gamma, ln_beta, W_in, b_in, W_ih, W_hh, b_ih, b_hh, W_out, b_out);
    vm_main<<<NBLOCKS, THREADS>>>(init_state, commands, out);
}

// round 12
// speedup vs baseline: 1.1501x; 1.1501x over previous
#include <cuda_runtime.h>

#define B_TOT 8192
#define T_STEPS 256
#define SD 12          // state dim
#define AD 4           // action dim
#define DD 16          // D = SD + AD
#define HH 16          // hidden
#define GG 64          // 4*H

#define WPB 2                      // warps (= batches) per block
#define THREADS (WPB * 32)
#define NBLOCKS (B_TOT / WPB)

typedef unsigned long long ull;

// Per-lane packed weights. lane = hi*16 + j owns gate rows r0 (hi=0: i_j, hi=1: f_j)
// and r1 (hi=0: g_j, hi=1: o_j).
__device__ float2 g_WxL[32 * 16];
__device__ float2 g_WhL[32 * 16];
__device__ float4 g_SBL[32];                    // (S_r0, S_r1, B_r0, B_r1)
__device__ __align__(16) float2 g_WoL[SD * 8];  // W_out packed pairs, row-major
__device__ float  g_boL[SD];

__global__ void vm_prep(const float* __restrict__ ln_gamma,
                        const float* __restrict__ ln_beta,
                        const float* __restrict__ W_in,   // [H][D]
                        const float* __restrict__ b_in,   // [H]
                        const float* __restrict__ W_ih,   // [G][H]
                        const float* __restrict__ W_hh,   // [G][H]
                        const float* __restrict__ b_ih,
                        const float* __restrict__ b_hh,
                        const float* __restrict__ W_out,  // [SD][H]
                        const float* __restrict__ b_out)
{
    int r = threadIdx.x;   // gate row 0..63
    if (r < GG) {
        int j    = r & 15;
        int hi   = (r >> 4) & 1;
        int s    = r >> 5;
        int lane = hi * 16 + j;
        float wp[DD];
        float S = 0.f, bB = 0.f;
        for (int d = 0; d < DD; d++) {
            float acc = 0.f;
            for (int k = 0; k < HH; k++) acc += W_ih[r * HH + k] * W_in[k * DD + d];
            wp[d] = acc * ln_gamma[d];             // fold gamma
            bB += acc * ln_beta[d];                // fold beta
            S += wp[d];
        }
        float bi = 0.f;
        for (int k = 0; k < HH; k++) bi += W_ih[r * HH + k] * b_in[k];
        ((float*)&g_SBL[lane])[s]     = S;
        ((float*)&g_SBL[lane])[2 + s] = bB + bi + b_ih[r] + b_hh[r];
        for (int p = 0; p < 8; p++) {
            g_WxL[lane * 16 + s * 8 + p] = make_float2(wp[2 * p], wp[2 * p + 1]);
            g_WhL[lane * 16 + s * 8 + p] = make_float2(W_hh[r * HH + 2 * p],
                                                       W_hh[r * HH + 2 * p + 1]);
        }
    }
    if (r < SD) {
        for (int p = 0; p < 8; p++)
            g_WoL[r * 8 + p] = make_float2(W_out[r * HH + 2 * p], W_out[r * HH + 2 * p + 1]);
        g_boL[r] = b_out[r];
    }
}

__device__ __forceinline__ void fma2(ull& acc, ull w, ull x) {
    asm("fma.rn.f32x2 %0, %1, %2, %0;" : "+l"(acc) : "l"(w), "l"(x));
}
__device__ __forceinline__ void add2(ull& acc, ull x) {
    asm("add.rn.f32x2 %0, %0, %1;" : "+l"(acc) : "l"(x));
}
__device__ __forceinline__ ull mul2(ull a, ull b) {
    ull r; asm("mul.rn.f32x2 %0, %1, %2;" : "=l"(r) : "l"(a), "l"(b)); return r;
}
__device__ __forceinline__ float2 up(ull v) {
    float2 r; asm("mov.b64 {%0, %1}, %2;" : "=f"(r.x), "=f"(r.y) : "l"(v)); return r;
}
__device__ __forceinline__ float ex2_(float x) {
    float r; asm("ex2.approx.f32 %0, %1;" : "=f"(r) : "f"(x)); return r;
}
__device__ __forceinline__ float rcp_(float x) {
    float r; asm("rcp.approx.f32 %0, %1;" : "=f"(r) : "f"(x)); return r;
}
__device__ __forceinline__ float sigm(float x) {
    return rcp_(1.f + ex2_(x * -1.44269504f));
}
__device__ __forceinline__ float tanh5(float x) {
    return fmaf(-2.f, rcp_(1.f + ex2_(x * 2.88539008f)), 1.f);
}

__global__ __launch_bounds__(THREADS, 10) void vm_main(
    const float* __restrict__ init_state,   // [B][1][SD]
    const float* __restrict__ commands,     // [B][T][AD]
    float* __restrict__ out)                // [B][T][SD]
{
    __shared__ __align__(16) float xbuf[WPB][16];
    __shared__ __align__(16) float hbuf[WPB][16];
    __shared__ ulonglong2 sWo[SD * 5];   // stride-5 quads: <=2-way bank conflict
    __shared__ float sbo[SD];

    int tid  = threadIdx.x;
    int w    = tid >> 5;     // warp in block = local batch
    int lane = tid & 31;
    int j    = lane & 15;
    int hi   = lane >> 4;
    int b    = blockIdx.x * WPB + w;

    // stage W_out into padded smem
    {
        const ulonglong2* gq = (const ulonglong2*)g_WoL;
        for (int i = tid; i < SD * 4; i += THREADS)
            sWo[(i >> 2) * 5 + (i & 3)] = gq[i];
        for (int i = tid; i < SD; i += THREADS) sbo[i] = g_boL[i];
    }

    // loop-invariant gate weights in registers
    ull Wx[16], Wh[16];
    const ull* wx = (const ull*)g_WxL + lane * 16;
    const ull* wh = (const ull*)g_WhL + lane * 16;
    #pragma unroll
    for (int i = 0; i < 16; i++) { Wx[i] = wx[i]; Wh[i] = wh[i]; }
    float4 SB = g_SBL[lane];

    int  jw      = (j < SD) ? j : 0;
    bool stlane  = (hi == 0) && (j < SD);
    bool cmdlane = (hi == 1) && (j >= SD);
    float kk     = hi ? -1.44269504f : 2.88539008f;   // sigm vs tanh exponent scale

    float st = 0.f;
    if (stlane) st = init_state[b * SD + j];
    float c = 0.f;
    ull a0h = 0ULL, a1h = 0ULL;     // Wh·h carried from previous step (h(-1)=0)

    const float* cmdp = commands + (size_t)b * (T_STEPS * AD);
    float*       outp = out      + (size_t)b * (T_STEPS * SD);
    int ci = j - SD;   // command component for cmdlane

    // x for t=0 ; prefetch cmds for t=1..4
    if (stlane)  xbuf[w][j] = st;
    if (cmdlane) xbuf[w][j] = cmdp[ci];
    float cb0 = 0.f, cb1 = 0.f, cb2 = 0.f, cb3 = 0.f;
    if (cmdlane) {
        cb0 = cmdp[1 * AD + ci];
        cb1 = cmdp[2 * AD + ci];
        cb2 = cmdp[3 * AD + ci];
        cb3 = cmdp[4 * AD + ci];
    }
    __syncthreads();   // sWo + xbuf visible

    const ulonglong2* xq4 = (const ulonglong2*)xbuf[w];
    const ulonglong2* hq4 = (const ulonglong2*)hbuf[w];
    const ulonglong2* wop = sWo + jw * 5;
    float bo = sbo[jw];

    int  p16 = (j >= 1 && j <= 6) ? (j + ((j & 1) ? 1 : -1)) : j;
    bool isc = (j >= 1 && j <= 6);

    auto step = [&](int t, float cnext) {
        // ---- x-pass: stream x quads (static), fuse LN stats + x gate dots ----
        ulonglong2 v = xq4[0];
        ull sa  = v.x;
        ull qa  = mul2(v.x, v.x);
        add2(sa, v.y); fma2(qa, v.y, v.y);
        ull a0x = mul2(Wx[0], v.x); fma2(a0x, Wx[1], v.y);
        ull a1x = mul2(Wx[8], v.x); fma2(a1x, Wx[9], v.y);
        #pragma unroll
        for (int q = 1; q < 4; q++) {
            v = xq4[q];
            add2(sa, v.x); fma2(qa, v.x, v.x);
            add2(sa, v.y); fma2(qa, v.y, v.y);
            fma2(a0x, Wx[2 * q],     v.x); fma2(a0x, Wx[2 * q + 1],     v.y);
            fma2(a1x, Wx[8 + 2 * q], v.x); fma2(a1x, Wx[8 + 2 * q + 1], v.y);
        }
        float2 su = up(sa), qu = up(qa);
        float mu   = (su.x + su.y) * 0.0625f;
        float var  = fmaf(-mu, mu, (qu.x + qu.y) * 0.0625f);
        float rstd = rsqrtf(var + 1e-5f);

        float2 u0 = up(a0x), u1 = up(a1x);
        float2 v0 = up(a0h), v1p = up(a1h);   // h-dot carried from previous step
        float g0 = fmaf(rstd, fmaf(-mu, SB.x, u0.x + u0.y), SB.z) + (v0.x + v0.y);
        float g1 = fmaf(rstd, fmaf(-mu, SB.y, u1.x + u1.y), SB.w) + (v1p.x + v1p.y);

        // ---- activations: hi=0 -> (sig i, tanh g) ; hi=1 -> (sig f, sig o) ----
        float sA = sigm(g0);
        float r1 = rcp_(1.f + ex2_(g1 * kk));
        float v1 = hi ? r1 : fmaf(-2.f, r1, 1.f);
        float a  = sA * v1;                               // sig(i)*tanh(g) on hi=0
        float send1 = hi ? sA : a;
        float fs = __shfl_xor_sync(0xffffffffu, send1, 16);  // hi=0 gets sig(f)
        float os = __shfl_xor_sync(0xffffffffu, v1, 16);     // hi=0 gets sig(o)
        c = fmaf(fs, c, a);
        float h = os * tanh5(c);

        if (hi == 0) hbuf[w][j] = h;
        __syncwarp();

        // ---- h-pass (static order): next step's Wh·h + full Wout dot ----
        ulonglong2 hv, wv;
        hv = hq4[0];
        a0h = mul2(Wh[0], hv.x); fma2(a0h, Wh[1], hv.y);
        a1h = mul2(Wh[8], hv.x); fma2(a1h, Wh[9], hv.y);
        wv = wop[0];
        ull ao0 = mul2(wv.x, hv.x); fma2(ao0, wv.y, hv.y);

        hv = hq4[1];
        fma2(a0h, Wh[2], hv.x); fma2(a0h, Wh[3], hv.y);
        fma2(a1h, Wh[10], hv.x); fma2(a1h, Wh[11], hv.y);
        wv = wop[1];
        fma2(ao0, wv.x, hv.x); fma2(ao0, wv.y, hv.y);

        hv = hq4[2];
        fma2(a0h, Wh[4], hv.x); fma2(a0h, Wh[5], hv.y);
        fma2(a1h, Wh[12], hv.x); fma2(a1h, Wh[13], hv.y);
        wv = wop[2];
        ull ao1 = mul2(wv.x, hv.x); fma2(ao1, wv.y, hv.y);

        hv = hq4[3];
        fma2(a0h, Wh[6], hv.x); fma2(a0h, Wh[7], hv.y);
        fma2(a1h, Wh[14], hv.x); fma2(a1h, Wh[15], hv.y);
        wv = wop[3];
        fma2(ao1, wv.x, hv.x); fma2(ao1, wv.y, hv.y);

        add2(ao0, ao1);
        float2 aou = up(ao0);
        st = st + (aou.x + aou.y) + bo;

        // sincos renorm, branch-free
        float other = __shfl_sync(0xffffffffu, st, p16, 16);
        float rn = rsqrtf(fmaf(st, st, other * other));
        st = isc ? st * rn : st;

        if (stlane) { outp[t * SD + j] = st; xbuf[w][j] = st; }
        if (cmdlane) xbuf[w][j] = cnext;
        __syncwarp();
    };

    for (int tb = 0; tb < T_STEPS; tb += 4) {
        // prefetch commands for steps tb+5 .. tb+8 (clamped)
        float n0 = 0.f, n1 = 0.f, n2 = 0.f, n3 = 0.f;
        if (cmdlane) {
            int i0 = tb + 5; if (i0 > T_STEPS - 1) i0 = T_STEPS - 1;
            int i1 = tb + 6; if (i1 > T_STEPS - 1) i1 = T_STEPS - 1;
            int i2 = tb + 7; if (i2 > T_STEPS - 1) i2 = T_STEPS - 1;
            int i3 = tb + 8; if (i3 > T_STEPS - 1) i3 = T_STEPS - 1;
            n0 = cmdp[i0 * AD + ci];
            n1 = cmdp[i1 * AD + ci];
            n2 = cmdp[i2 * AD + ci];
            n3 = cmdp[i3 * AD + ci];
        }
        step(tb + 0, cb0);
        step(tb + 1, cb1);
        step(tb + 2, cb2);
        step(tb + 3, cb3);
        cb0 = n0; cb1 = n1; cb2 = n2; cb3 = n3;
    }
}

extern "C" void kernel_launch(void* const* d_in, const int* in_sizes, int n_in,
                              void* d_out, int out_size) {
    const float* init_state = (const float*)d_in[0];
    const float* commands   = (const float*)d_in[1];
    const float* ln_gamma   = (const float*)d_in[2];
    const float* ln_beta    = (const float*)d_in[3];
    const float* W_in       = (const float*)d_in[4];
    const float* b_in       = (const float*)d_in[5];
    const float* W_ih       = (const float*)d_in[6];
    const float* W_hh       = (const float*)d_in[7];
    const float* b_ih       = (const float*)d_in[8];
    const float* b_hh       = (const float*)d_in[9];
    const float* W_out      = (const float*)d_in[10];
    const float* b_out      = (const float*)d_in[11];
    float* out = (float*)d_out;

    vm_prep<<<1, 64>>>(ln_gamma, ln_beta, W_in, b_in, W_ih, W_hh, b_ih, b_hh, W_out, b_out);
    vm_main<<<NBLOCKS, THREADS>>>(init_state, commands, out);
}